// round 3
// baseline (speedup 1.0000x reference)
#include <cuda_runtime.h>
#include <cstdint>
#include <cstddef>

#define SEQT 2048
#define NTAG 12
#define STARTT 10
#define STOPT 11
#define NEGV -10000.0f

// ---------------- scratch (device globals; no allocation) ----------------
__device__ float g_pre[2][SEQT][1024];      // 16 MB: input projections (i,f,g,o rows)
__device__ float g_hs[SEQT][512];           // 4 MB: [hf | hb] per timestep
__device__ float g_feats[SEQT][NTAG];
__device__ float g_P[SEQT / 32][NTAG][NTAG];

// ---------------- helpers ----------------
__device__ __forceinline__ unsigned long long fma2(unsigned long long a, unsigned long long b,
                                                   unsigned long long c) {
    unsigned long long d;
    asm("fma.rn.f32x2 %0, %1, %2, %3;" : "=l"(d) : "l"(a), "l"(b), "l"(c));
    return d;
}
__device__ __forceinline__ unsigned long long add2(unsigned long long a, unsigned long long b) {
    unsigned long long d;
    asm("add.rn.f32x2 %0, %1, %2;" : "=l"(d) : "l"(a), "l"(b));
    return d;
}
__device__ __forceinline__ float2 unpack2(unsigned long long u) {
    float2 f;
    asm("mov.b64 {%0, %1}, %2;" : "=f"(f.x), "=f"(f.y) : "l"(u));
    return f;
}
__device__ __forceinline__ unsigned smem_u32(const void* p) {
    return (unsigned)__cvta_generic_to_shared(p);
}
__device__ __forceinline__ unsigned ctarank() {
    unsigned r;
    asm("mov.u32 %0, %%cluster_ctarank;" : "=r"(r));
    return r;
}
__device__ __forceinline__ unsigned mapa_u32(unsigned local_addr, unsigned rank) {
    unsigned r;
    asm("mapa.shared::cluster.u32 %0, %1, %2;" : "=r"(r) : "r"(local_addr), "r"(rank));
    return r;
}
__device__ __forceinline__ float sigf(float x) { return 1.f / (1.f + __expf(-x)); }
__device__ __forceinline__ float tanh_fast(float x) { return 2.f / (1.f + __expf(-2.f * x)) - 1.f; }

#define CLUSTER_SYNC_()                                                \
    do {                                                               \
        asm volatile("barrier.cluster.arrive.aligned;" ::: "memory");  \
        asm volatile("barrier.cluster.wait.aligned;" ::: "memory");    \
    } while (0)

// cluster-scope acquire parity wait on a local-CTA mbarrier
__device__ __forceinline__ void mbar_wait_cluster(unsigned addr, int phase) {
    unsigned done;
    asm volatile(
        "{\n\t.reg .pred p;\n\t"
        "mbarrier.try_wait.parity.acquire.cluster.shared::cta.b64 p, [%1], %2;\n\t"
        "selp.b32 %0, 1, 0, p;\n\t}"
        : "=r"(done) : "r"(addr), "r"((unsigned)phase) : "memory");
    if (!done) {
        asm volatile(
            "{\n\t.reg .pred P1;\n\t"
            "WL_%=:\n\t"
            "mbarrier.try_wait.parity.acquire.cluster.shared::cta.b64 P1, [%0], %1, 0x989680;\n\t"
            "@P1 bra.uni WD_%=;\n\t"
            "bra.uni WL_%=;\n\t"
            "WD_%=:\n\t}"
            :: "r"(addr), "r"((unsigned)phase) : "memory");
    }
}

// ---------------- kernel A: embedding gather + input projection ----------------
// pre[dir][t][row] = sum_e embed[sent[t]][e] * Wih[row][e] + bih[row] + bhh[row]
// grid 512 (256 per dir, 8 timesteps each), 256 threads, 4 rows/thread, f32x2 math.
__global__ void __launch_bounds__(256) proj_kernel(
    const int* __restrict__ sent, const float* __restrict__ embed,
    const float* __restrict__ Wf, const float* __restrict__ bihf, const float* __restrict__ bhhf,
    const float* __restrict__ Wb, const float* __restrict__ bihb, const float* __restrict__ bhhb) {
    __shared__ __align__(16) float xs[8][256];
    int bx = blockIdx.x;
    int dir = bx >> 8;
    int t0 = (bx & 255) * 8;
    int tid = threadIdx.x;
#pragma unroll
    for (int i = 0; i < 8; i++) {
        xs[i][tid] = embed[(size_t)sent[t0 + i] * 256 + tid];
    }
    __syncthreads();
    const float* W = dir ? Wb : Wf;
    const float* bi = dir ? bihb : bihf;
    const float* bh = dir ? bhhb : bhhf;
    int r0 = tid * 4;
    unsigned long long acc2[8][4];
#pragma unroll
    for (int t = 0; t < 8; t++)
#pragma unroll
        for (int r = 0; r < 4; r++) acc2[t][r] = 0ull;

#pragma unroll 1
    for (int e = 0; e < 256; e += 4) {
        ulonglong2 w0 = *(const ulonglong2*)(W + (size_t)(r0 + 0) * 256 + e);
        ulonglong2 w1 = *(const ulonglong2*)(W + (size_t)(r0 + 1) * 256 + e);
        ulonglong2 w2 = *(const ulonglong2*)(W + (size_t)(r0 + 2) * 256 + e);
        ulonglong2 w3 = *(const ulonglong2*)(W + (size_t)(r0 + 3) * 256 + e);
#pragma unroll
        for (int t = 0; t < 8; t++) {
            ulonglong2 xv = *(const ulonglong2*)(&xs[t][e]);
            acc2[t][0] = fma2(w0.x, xv.x, acc2[t][0]);
            acc2[t][0] = fma2(w0.y, xv.y, acc2[t][0]);
            acc2[t][1] = fma2(w1.x, xv.x, acc2[t][1]);
            acc2[t][1] = fma2(w1.y, xv.y, acc2[t][1]);
            acc2[t][2] = fma2(w2.x, xv.x, acc2[t][2]);
            acc2[t][2] = fma2(w2.y, xv.y, acc2[t][2]);
            acc2[t][3] = fma2(w3.x, xv.x, acc2[t][3]);
            acc2[t][3] = fma2(w3.y, xv.y, acc2[t][3]);
        }
    }
    float bs[4];
#pragma unroll
    for (int r = 0; r < 4; r++) bs[r] = bi[r0 + r] + bh[r0 + r];
#pragma unroll
    for (int t = 0; t < 8; t++) {
        float4 o;
        float2 p0 = unpack2(acc2[t][0]);
        float2 p1 = unpack2(acc2[t][1]);
        float2 p2 = unpack2(acc2[t][2]);
        float2 p3 = unpack2(acc2[t][3]);
        o.x = p0.x + p0.y + bs[0];
        o.y = p1.x + p1.y + bs[1];
        o.z = p2.x + p2.y + bs[2];
        o.w = p3.x + p3.y + bs[3];
        *(float4*)(&g_pre[dir][t0 + t][r0]) = o;
    }
}

// ---------------- kernel B: LSTM recurrence ----------------
// grid = 16 CTAs, cluster 8. CTAs 0-7: forward dir; 8-15: backward dir.
// Each CTA owns 32 hidden units (128 gate rows). Thread t: l = t&127 row,
// seg = t>>7 (64-wide K segment). Weights register-resident as f32x2.
// h exchanged via st.shared::cluster + per-lane mbarrier.arrive.release.cluster;
// consumers try_wait.parity.acquire.cluster. Double-buffered hbuf + mbar.
// pre[t] is software-pipelined (prefetch next step before the wait).
__global__ void __cluster_dims__(8, 1, 1) __launch_bounds__(512, 1)
lstm_kernel(const float* __restrict__ Whh_f, const float* __restrict__ Whh_b,
            const float* __restrict__ h0, const float* __restrict__ c0) {
    __shared__ __align__(16) float hbuf[2][256];
    __shared__ float part[512];
    __shared__ float act[128];
    __shared__ __align__(8) unsigned long long mbar[2];

    int tid = threadIdx.x;
    int dir = blockIdx.x >> 3;
    unsigned rank = ctarank();  // 0..7
    int l = tid & 127;
    int seg = tid >> 7;
    int gate = l >> 5;
    int jl = l & 31;
    int grow = gate * 256 + (int)rank * 32 + jl;  // global gate row 0..1023

    const float* Whh = dir ? Whh_b : Whh_f;
    unsigned long long w2[32];
    {
        const ulonglong2* wp = (const ulonglong2*)(Whh + (size_t)grow * 256 + seg * 64);
#pragma unroll
        for (int i = 0; i < 16; i++) {
            ulonglong2 v = wp[i];
            w2[2 * i] = v.x;
            w2[2 * i + 1] = v.y;
        }
    }

    if (tid == 0) {
        asm volatile("mbarrier.init.shared.b64 [%0], %1;" ::
                     "r"(smem_u32(&mbar[0])), "r"(256u) : "memory");
        asm volatile("mbarrier.init.shared.b64 [%0], %1;" ::
                     "r"(smem_u32(&mbar[1])), "r"(256u) : "memory");
        asm volatile("fence.mbarrier_init.release.cluster;" ::: "memory");
    }
    if (tid < 256) hbuf[0][tid] = h0[dir * 256 + tid];
    float c = 0.f;
    if (tid < 32) c = c0[dir * 256 + (int)rank * 32 + tid];

    // precompute remote addresses (producers only): hbuf slot + mbar base per peer
    unsigned ra_h[8], ra_m[8];
    if (tid < 32) {
        unsigned lh = smem_u32(&hbuf[0][(int)rank * 32 + tid]);
        unsigned lm = smem_u32(&mbar[0]);
#pragma unroll
        for (int r = 0; r < 8; r++) {
            ra_h[r] = mapa_u32(lh, (unsigned)r);
            ra_m[r] = mapa_u32(lm, (unsigned)r);
        }
    }
    const float* pre = &g_pre[dir][0][0];

    __syncthreads();
    CLUSTER_SYNC_();

    int ph0 = 0, ph1 = 0;
    float pv = 0.f;
    if (tid < 128) pv = pre[(size_t)(dir ? SEQT - 1 : 0) * 1024 + grow];

#pragma unroll 1
    for (int s = 0; s < SEQT; s++) {
        int par = s & 1;
        // prefetch next step's input projection (hide L2/DRAM behind the wait+compute)
        float pv_next = 0.f;
        if (tid < 128 && s + 1 < SEQT) {
            int tn = dir ? (SEQT - 2 - s) : (s + 1);
            pv_next = pre[(size_t)tn * 1024 + grow];
        }
        if (s > 0) {
            if (par) {
                mbar_wait_cluster(smem_u32(&mbar[1]), ph1);
                ph1 ^= 1;
            } else {
                mbar_wait_cluster(smem_u32(&mbar[0]), ph0);
                ph0 ^= 1;
            }
        }

        const ulonglong2* hp = (const ulonglong2*)(&hbuf[par][seg * 64]);
        unsigned long long a0 = 0ull, a1 = 0ull, a2 = 0ull, a3 = 0ull;
#pragma unroll
        for (int i = 0; i < 16; i += 2) {
            ulonglong2 v0 = hp[i];
            ulonglong2 v1 = hp[i + 1];
            a0 = fma2(w2[2 * i + 0], v0.x, a0);
            a1 = fma2(w2[2 * i + 1], v0.y, a1);
            a2 = fma2(w2[2 * i + 2], v1.x, a2);
            a3 = fma2(w2[2 * i + 3], v1.y, a3);
        }
        a0 = add2(a0, a1);
        a2 = add2(a2, a3);
        a0 = add2(a0, a2);
        float2 fa = unpack2(a0);
        part[tid] = fa.x + fa.y;
        __syncthreads();

        if (tid < 128) {
            float g = part[tid] + part[tid + 128] + part[tid + 256] + part[tid + 384] + pv;
            act[tid] = (gate == 2) ? tanh_fast(g) : sigf(g);
        }
        __syncthreads();

        if (tid < 32) {
            float gi = act[tid];
            float gf = act[32 + tid];
            float gg = act[64 + tid];
            float go = act[96 + tid];
            c = gf * c + gi * gg;
            float h = go * tanh_fast(c);
            int t = dir ? (SEQT - 1 - s) : s;
            g_hs[t][dir * 256 + (int)rank * 32 + tid] = h;
            if (s + 1 < SEQT) {
                unsigned hoff = (unsigned)((par ^ 1) * 256 * 4);
                unsigned moff = (unsigned)((par ^ 1) * 8);
#pragma unroll
                for (int r = 0; r < 8; r++) {
                    asm volatile("st.shared::cluster.f32 [%0], %1;" ::
                                 "r"(ra_h[r] + hoff), "f"(h) : "memory");
                    asm volatile(
                        "mbarrier.arrive.release.cluster.shared::cluster.b64 _, [%0];" ::
                        "r"(ra_m[r] + moff) : "memory");
                }
            }
        }
        pv = pv_next;
    }
    CLUSTER_SYNC_();
}

// ---------------- kernel C: emissions ----------------
// feats[t][n] = sum_k hs[t][k] * W_out[n][k] + b_out[n]
__global__ void __launch_bounds__(128) feats_kernel(const float* __restrict__ W_out,
                                                    const float* __restrict__ b_out) {
    int t = blockIdx.x;
    __shared__ __align__(16) float hs_s[512];
    int tid = threadIdx.x;
    ((float4*)hs_s)[tid] = ((const float4*)&g_hs[t][0])[tid];
    __syncthreads();
    int w = tid >> 5, lane = tid & 31;
    for (int tag = w; tag < NTAG; tag += 4) {
        float a = 0.f;
#pragma unroll
        for (int i = 0; i < 16; i++) {
            int k = lane + 32 * i;
            a = fmaf(hs_s[k], W_out[tag * 512 + k], a);
        }
#pragma unroll
        for (int off = 16; off > 0; off >>= 1) a += __shfl_xor_sync(0xffffffffu, a, off);
        if (lane == 0) g_feats[t][tag] = a + b_out[tag];
    }
}

// ---------------- kernel D: CRF chunked log-semiring products ----------------
// P_c = M_{t0+31} (x) ... (x) M_{t0}, M_t[n,p] = T[n,p] + emit_t[n]
__global__ void __launch_bounds__(144) crf_chunk_kernel(const float* __restrict__ trans) {
    __shared__ float T[NTAG][NTAG];
    __shared__ float P[2][NTAG][NTAG + 1];
    __shared__ float em[32][NTAG];
    int tid = threadIdx.x;
    int n = tid / NTAG, p = tid - n * NTAG;
    int t0 = blockIdx.x * 32;
    T[n][p] = trans[tid];
    for (int idx = tid; idx < 32 * NTAG; idx += 144)
        em[idx / NTAG][idx % NTAG] = g_feats[t0 + idx / NTAG][idx % NTAG];
    __syncthreads();
    P[0][n][p] = T[n][p] + em[0][n];
    __syncthreads();
    int cur = 0;
#pragma unroll 1
    for (int s = 1; s < 32; s++) {
        float m = -1e30f;
#pragma unroll
        for (int k = 0; k < NTAG; k++) m = fmaxf(m, T[n][k] + P[cur][k][p]);
        float sm = 0.f;
#pragma unroll
        for (int k = 0; k < NTAG; k++) sm += __expf(T[n][k] + P[cur][k][p] - m);
        P[cur ^ 1][n][p] = em[s][n] + m + logf(sm);
        __syncthreads();
        cur ^= 1;
    }
    g_P[blockIdx.x][n][p] = P[cur][n][p];
}

// ---------------- kernel E: final combine + gold score ----------------
__global__ void __launch_bounds__(256) crf_final_kernel(const int* __restrict__ tags,
                                                        const float* __restrict__ trans,
                                                        float* __restrict__ out) {
    __shared__ float red[256];
    __shared__ float v[NTAG], nv[NTAG];
    int tid = threadIdx.x;
    float gs = 0.f;
    for (int t = tid; t < SEQT; t += 256) {
        int tg = tags[t];
        int pv = (t == 0) ? STARTT : tags[t - 1];
        gs += trans[tg * NTAG + pv] + g_feats[t][tg];
    }
    red[tid] = gs;
    __syncthreads();
    for (int off = 128; off > 0; off >>= 1) {
        if (tid < off) red[tid] += red[tid + off];
        __syncthreads();
    }
    if (tid < NTAG) v[tid] = (tid == STARTT) ? 0.f : NEGV;
    __syncthreads();
#pragma unroll 1
    for (int cidx = 0; cidx < SEQT / 32; cidx++) {
        if (tid < NTAG) {
            float m = -1e30f;
#pragma unroll
            for (int p = 0; p < NTAG; p++) m = fmaxf(m, g_P[cidx][tid][p] + v[p]);
            float s = 0.f;
#pragma unroll
            for (int p = 0; p < NTAG; p++) s += __expf(g_P[cidx][tid][p] + v[p] - m);
            nv[tid] = m + logf(s);
        }
        __syncthreads();
        if (tid < NTAG) v[tid] = nv[tid];
        __syncthreads();
    }
    if (tid == 0) {
        float m = -1e30f;
#pragma unroll
        for (int n = 0; n < NTAG; n++) m = fmaxf(m, v[n] + trans[STOPT * NTAG + n]);
        float s = 0.f;
#pragma unroll
        for (int n = 0; n < NTAG; n++) s += __expf(v[n] + trans[STOPT * NTAG + n] - m);
        float fwd = m + logf(s);
        float gold = red[0] + trans[STOPT * NTAG + tags[SEQT - 1]];
        out[0] = fwd - gold;
    }
}

// ---------------- launch ----------------
extern "C" void kernel_launch(void* const* d_in, const int* in_sizes, int n_in,
                              void* d_out, int out_size) {
    const int* sent = (const int*)d_in[0];
    const int* tags = (const int*)d_in[1];
    const float* embed = (const float*)d_in[2];
    const float* Wih_f = (const float*)d_in[3];
    const float* Whh_f = (const float*)d_in[4];
    const float* bih_f = (const float*)d_in[5];
    const float* bhh_f = (const float*)d_in[6];
    const float* Wih_b = (const float*)d_in[7];
    const float* Whh_b = (const float*)d_in[8];
    const float* bih_b = (const float*)d_in[9];
    const float* bhh_b = (const float*)d_in[10];
    const float* W_out = (const float*)d_in[11];
    const float* b_out = (const float*)d_in[12];
    const float* h0 = (const float*)d_in[13];
    const float* c0 = (const float*)d_in[14];
    const float* trans = (const float*)d_in[15];
    float* out = (float*)d_out;

    proj_kernel<<<512, 256>>>(sent, embed, Wih_f, bih_f, bhh_f, Wih_b, bih_b, bhh_b);
    lstm_kernel<<<16, 512>>>(Whh_f, Whh_b, h0, c0);
    feats_kernel<<<SEQT, 128>>>(W_out, b_out);
    crf_chunk_kernel<<<SEQT / 32, 144>>>(trans);
    crf_final_kernel<<<1, 256>>>(tags, trans, out);
}

// round 5
// speedup vs baseline: 1.6830x; 1.6830x over previous
#include <cuda_runtime.h>
#include <cstdint>
#include <cstddef>

#define SEQT 2048
#define NTAG 12
#define STARTT 10
#define STOPT 11
#define NEGV -10000.0f

// ---------------- scratch (device globals; no allocation) ----------------
__device__ float g_pre[2][SEQT][1024];      // 16 MB: input projections (i,f,g,o rows)
__device__ float g_hs[SEQT][512];           // 4 MB: [hf | hb] per timestep
__device__ float g_feats[SEQT][NTAG];
__device__ float g_P[SEQT / 32][NTAG][NTAG];

// ---------------- helpers ----------------
__device__ __forceinline__ unsigned long long fma2(unsigned long long a, unsigned long long b,
                                                   unsigned long long c) {
    unsigned long long d;
    asm("fma.rn.f32x2 %0, %1, %2, %3;" : "=l"(d) : "l"(a), "l"(b), "l"(c));
    return d;
}
__device__ __forceinline__ unsigned long long add2(unsigned long long a, unsigned long long b) {
    unsigned long long d;
    asm("add.rn.f32x2 %0, %1, %2;" : "=l"(d) : "l"(a), "l"(b));
    return d;
}
__device__ __forceinline__ float2 unpack2(unsigned long long u) {
    float2 f;
    asm("mov.b64 {%0, %1}, %2;" : "=f"(f.x), "=f"(f.y) : "l"(u));
    return f;
}
__device__ __forceinline__ unsigned smem_u32(const void* p) {
    return (unsigned)__cvta_generic_to_shared(p);
}
__device__ __forceinline__ unsigned ctarank() {
    unsigned r;
    asm("mov.u32 %0, %%cluster_ctarank;" : "=r"(r));
    return r;
}
__device__ __forceinline__ unsigned mapa_u32(unsigned local_addr, unsigned rank) {
    unsigned r;
    asm("mapa.shared::cluster.u32 %0, %1, %2;" : "=r"(r) : "r"(local_addr), "r"(rank));
    return r;
}
__device__ __forceinline__ float sigf(float x) { return 1.f / (1.f + __expf(-x)); }
__device__ __forceinline__ float tanh_fast(float x) { return 2.f / (1.f + __expf(-2.f * x)) - 1.f; }

#define CLUSTER_SYNC_()                                                \
    do {                                                               \
        asm volatile("barrier.cluster.arrive.aligned;" ::: "memory");  \
        asm volatile("barrier.cluster.wait.aligned;" ::: "memory");    \
    } while (0)

// ---------------- kernel A: embedding gather + input projection ----------------
__global__ void __launch_bounds__(256) proj_kernel(
    const int* __restrict__ sent, const float* __restrict__ embed,
    const float* __restrict__ Wf, const float* __restrict__ bihf, const float* __restrict__ bhhf,
    const float* __restrict__ Wb, const float* __restrict__ bihb, const float* __restrict__ bhhb) {
    __shared__ __align__(16) float xs[8][256];
    int bx = blockIdx.x;
    int dir = bx >> 8;
    int t0 = (bx & 255) * 8;
    int tid = threadIdx.x;
#pragma unroll
    for (int i = 0; i < 8; i++) {
        xs[i][tid] = embed[(size_t)sent[t0 + i] * 256 + tid];
    }
    __syncthreads();
    const float* W = dir ? Wb : Wf;
    const float* bi = dir ? bihb : bihf;
    const float* bh = dir ? bhhb : bhhf;
    int r0 = tid * 4;
    unsigned long long acc2[8][4];
#pragma unroll
    for (int t = 0; t < 8; t++)
#pragma unroll
        for (int r = 0; r < 4; r++) acc2[t][r] = 0ull;

#pragma unroll 1
    for (int e = 0; e < 256; e += 4) {
        ulonglong2 w0 = *(const ulonglong2*)(W + (size_t)(r0 + 0) * 256 + e);
        ulonglong2 w1 = *(const ulonglong2*)(W + (size_t)(r0 + 1) * 256 + e);
        ulonglong2 w2 = *(const ulonglong2*)(W + (size_t)(r0 + 2) * 256 + e);
        ulonglong2 w3 = *(const ulonglong2*)(W + (size_t)(r0 + 3) * 256 + e);
#pragma unroll
        for (int t = 0; t < 8; t++) {
            ulonglong2 xv = *(const ulonglong2*)(&xs[t][e]);
            acc2[t][0] = fma2(w0.x, xv.x, acc2[t][0]);
            acc2[t][0] = fma2(w0.y, xv.y, acc2[t][0]);
            acc2[t][1] = fma2(w1.x, xv.x, acc2[t][1]);
            acc2[t][1] = fma2(w1.y, xv.y, acc2[t][1]);
            acc2[t][2] = fma2(w2.x, xv.x, acc2[t][2]);
            acc2[t][2] = fma2(w2.y, xv.y, acc2[t][2]);
            acc2[t][3] = fma2(w3.x, xv.x, acc2[t][3]);
            acc2[t][3] = fma2(w3.y, xv.y, acc2[t][3]);
        }
    }
    float bs[4];
#pragma unroll
    for (int r = 0; r < 4; r++) bs[r] = bi[r0 + r] + bh[r0 + r];
#pragma unroll
    for (int t = 0; t < 8; t++) {
        float4 o;
        float2 p0 = unpack2(acc2[t][0]);
        float2 p1 = unpack2(acc2[t][1]);
        float2 p2 = unpack2(acc2[t][2]);
        float2 p3 = unpack2(acc2[t][3]);
        o.x = p0.x + p0.y + bs[0];
        o.y = p1.x + p1.y + bs[1];
        o.z = p2.x + p2.y + bs[2];
        o.w = p3.x + p3.y + bs[3];
        *(float4*)(&g_pre[dir][t0 + t][r0]) = o;
    }
}

// ---------------- kernel B: LSTM recurrence ----------------
// grid = 16 CTAs, cluster 8. CTAs 0-7: forward dir; 8-15: backward dir.
// Each CTA owns 32 hidden units (128 gate rows). 256 threads:
//   thread -> (j = wid*4 + (lane>>3), gate = (lane>>1)&3, seg = lane&1)
// Each thread computes a half-row dot (K=128, weights register-resident f32x2).
// seg pair combined with shfl_xor(1); i/f/g/o gathered with shfls (intra-warp).
// Base lanes (lane&7==0) hold c, compute h, push h to all 8 peer hbufs via
// weak st.shared::cluster. ONE barrier.cluster per step is the only sync
// (arrive = cluster-scope release, wait = acquire -> orders the DSMEM stores;
// double-buffered hbuf removes write-after-read hazards within a step).
// pre[t] is software-pipelined: next step's LDG issued right after the barrier.
__global__ void __cluster_dims__(8, 1, 1) __launch_bounds__(256, 1)
lstm_kernel(const float* __restrict__ Whh_f, const float* __restrict__ Whh_b,
            const float* __restrict__ h0, const float* __restrict__ c0) {
    __shared__ __align__(16) float hbuf[2][256];

    int tid = threadIdx.x;
    int dir = blockIdx.x >> 3;
    unsigned rank = ctarank();  // 0..7
    int wid = tid >> 5;
    int lane = tid & 31;
    int j = wid * 4 + (lane >> 3);        // 0..31 local hidden unit
    int gate = (lane >> 1) & 3;           // 0..3
    int seg = lane & 1;                   // K half
    int grow = gate * 256 + (int)rank * 32 + j;  // global gate row 0..1023
    int base = lane & 24;                 // lane of (j, gate0, seg0)

    const float* Whh = dir ? Whh_b : Whh_f;
    // this thread's 128 weights as 64 packed f32x2
    unsigned long long w2[64];
    {
        const ulonglong2* wp = (const ulonglong2*)(Whh + (size_t)grow * 256 + seg * 128);
#pragma unroll
        for (int i = 0; i < 32; i++) {
            ulonglong2 v = wp[i];
            w2[2 * i] = v.x;
            w2[2 * i + 1] = v.y;
        }
    }

    hbuf[0][tid] = h0[dir * 256 + tid];
    float c = 0.f;
    if ((lane & 7) == 0) c = c0[dir * 256 + (int)rank * 32 + j];

    // producers (base lanes): peer hbuf slot addresses for my h value
    unsigned ra_h[8];
    if ((lane & 7) == 0) {
        unsigned lh = smem_u32(&hbuf[0][(int)rank * 32 + j]);
#pragma unroll
        for (int r = 0; r < 8; r++) ra_h[r] = mapa_u32(lh, (unsigned)r);
    }
    const float* pre = &g_pre[dir][0][0];

    __syncthreads();
    CLUSTER_SYNC_();

    float pv = 0.f;
    if (seg == 0) pv = pre[(size_t)(dir ? SEQT - 1 : 0) * 1024 + grow];

#pragma unroll 1
    for (int s = 0; s < SEQT; s++) {
        int par = s & 1;
        // prefetch next step's input projection (hidden behind matvec + barrier)
        float pv_next = 0.f;
        if (seg == 0 && s + 1 < SEQT) {
            int tn = dir ? (SEQT - 2 - s) : (s + 1);
            pv_next = pre[(size_t)tn * 1024 + grow];
        }

        // half-row dot product (weights in registers, h broadcast from SMEM)
        const ulonglong2* hp = (const ulonglong2*)(&hbuf[par][seg * 128]);
        unsigned long long a0 = 0ull, a1 = 0ull, a2 = 0ull, a3 = 0ull;
#pragma unroll
        for (int i = 0; i < 32; i += 2) {
            ulonglong2 v0 = hp[i];
            ulonglong2 v1 = hp[i + 1];
            a0 = fma2(w2[2 * i + 0], v0.x, a0);
            a1 = fma2(w2[2 * i + 1], v0.y, a1);
            a2 = fma2(w2[2 * i + 2], v1.x, a2);
            a3 = fma2(w2[2 * i + 3], v1.y, a3);
        }
        a0 = add2(a0, a1);
        a2 = add2(a2, a3);
        a0 = add2(a0, a2);
        float2 fa = unpack2(a0);
        float sum = fa.x + fa.y;
        sum += __shfl_xor_sync(0xffffffffu, sum, 1);  // combine K halves
        float g = sum + pv;                            // valid on seg0 lanes
        float av = (gate == 2) ? tanh_fast(g) : sigf(g);

        float gi = __shfl_sync(0xffffffffu, av, base + 0);
        float gf = __shfl_sync(0xffffffffu, av, base + 2);
        float gg = __shfl_sync(0xffffffffu, av, base + 4);
        float go = __shfl_sync(0xffffffffu, av, base + 6);

        if ((lane & 7) == 0) {
            c = gf * c + gi * gg;
            float h = go * tanh_fast(c);
            int t = dir ? (SEQT - 1 - s) : s;
            g_hs[t][dir * 256 + (int)rank * 32 + j] = h;
            if (s + 1 < SEQT) {
                unsigned hoff = (unsigned)((par ^ 1) * 1024);
#pragma unroll
                for (int r = 0; r < 8; r++) {
                    asm volatile("st.shared::cluster.f32 [%0], %1;" ::
                                 "r"(ra_h[r] + hoff), "f"(h) : "memory");
                }
            }
        }
        CLUSTER_SYNC_();  // release DSMEM stores + acquire for next step
        pv = pv_next;
    }
}

// ---------------- kernel C: emissions ----------------
__global__ void __launch_bounds__(128) feats_kernel(const float* __restrict__ W_out,
                                                    const float* __restrict__ b_out) {
    int t = blockIdx.x;
    __shared__ __align__(16) float hs_s[512];
    int tid = threadIdx.x;
    ((float4*)hs_s)[tid] = ((const float4*)&g_hs[t][0])[tid];
    __syncthreads();
    int w = tid >> 5, lane = tid & 31;
    for (int tag = w; tag < NTAG; tag += 4) {
        float a = 0.f;
#pragma unroll
        for (int i = 0; i < 16; i++) {
            int k = lane + 32 * i;
            a = fmaf(hs_s[k], W_out[tag * 512 + k], a);
        }
#pragma unroll
        for (int off = 16; off > 0; off >>= 1) a += __shfl_xor_sync(0xffffffffu, a, off);
        if (lane == 0) g_feats[t][tag] = a + b_out[tag];
    }
}

// ---------------- kernel D: CRF chunked log-semiring products ----------------
__global__ void __launch_bounds__(144) crf_chunk_kernel(const float* __restrict__ trans) {
    __shared__ float T[NTAG][NTAG];
    __shared__ float P[2][NTAG][NTAG + 1];
    __shared__ float em[32][NTAG];
    int tid = threadIdx.x;
    int n = tid / NTAG, p = tid - n * NTAG;
    int t0 = blockIdx.x * 32;
    T[n][p] = trans[tid];
    for (int idx = tid; idx < 32 * NTAG; idx += 144)
        em[idx / NTAG][idx % NTAG] = g_feats[t0 + idx / NTAG][idx % NTAG];
    __syncthreads();
    P[0][n][p] = T[n][p] + em[0][n];
    __syncthreads();
    int cur = 0;
#pragma unroll 1
    for (int s = 1; s < 32; s++) {
        float m = -1e30f;
#pragma unroll
        for (int k = 0; k < NTAG; k++) m = fmaxf(m, T[n][k] + P[cur][k][p]);
        float sm = 0.f;
#pragma unroll
        for (int k = 0; k < NTAG; k++) sm += __expf(T[n][k] + P[cur][k][p] - m);
        P[cur ^ 1][n][p] = em[s][n] + m + logf(sm);
        __syncthreads();
        cur ^= 1;
    }
    g_P[blockIdx.x][n][p] = P[cur][n][p];
}

// ---------------- kernel E: final combine + gold score ----------------
__global__ void __launch_bounds__(256) crf_final_kernel(const int* __restrict__ tags,
                                                        const float* __restrict__ trans,
                                                        float* __restrict__ out) {
    __shared__ float red[256];
    __shared__ float v[NTAG], nv[NTAG];
    int tid = threadIdx.x;
    float gs = 0.f;
    for (int t = tid; t < SEQT; t += 256) {
        int tg = tags[t];
        int pv = (t == 0) ? STARTT : tags[t - 1];
        gs += trans[tg * NTAG + pv] + g_feats[t][tg];
    }
    red[tid] = gs;
    __syncthreads();
    for (int off = 128; off > 0; off >>= 1) {
        if (tid < off) red[tid] += red[tid + off];
        __syncthreads();
    }
    if (tid < NTAG) v[tid] = (tid == STARTT) ? 0.f : NEGV;
    __syncthreads();
#pragma unroll 1
    for (int cidx = 0; cidx < SEQT / 32; cidx++) {
        if (tid < NTAG) {
            float m = -1e30f;
#pragma unroll
            for (int p = 0; p < NTAG; p++) m = fmaxf(m, g_P[cidx][tid][p] + v[p]);
            float s = 0.f;
#pragma unroll
            for (int p = 0; p < NTAG; p++) s += __expf(g_P[cidx][tid][p] + v[p] - m);
            nv[tid] = m + logf(s);
        }
        __syncthreads();
        if (tid < NTAG) v[tid] = nv[tid];
        __syncthreads();
    }
    if (tid == 0) {
        float m = -1e30f;
#pragma unroll
        for (int n = 0; n < NTAG; n++) m = fmaxf(m, v[n] + trans[STOPT * NTAG + n]);
        float s = 0.f;
#pragma unroll
        for (int n = 0; n < NTAG; n++) s += __expf(v[n] + trans[STOPT * NTAG + n] - m);
        float fwd = m + logf(s);
        float gold = red[0] + trans[STOPT * NTAG + tags[SEQT - 1]];
        out[0] = fwd - gold;
    }
}

// ---------------- launch ----------------
extern "C" void kernel_launch(void* const* d_in, const int* in_sizes, int n_in,
                              void* d_out, int out_size) {
    const int* sent = (const int*)d_in[0];
    const int* tags = (const int*)d_in[1];
    const float* embed = (const float*)d_in[2];
    const float* Wih_f = (const float*)d_in[3];
    const float* Whh_f = (const float*)d_in[4];
    const float* bih_f = (const float*)d_in[5];
    const float* bhh_f = (const float*)d_in[6];
    const float* Wih_b = (const float*)d_in[7];
    const float* Whh_b = (const float*)d_in[8];
    const float* bih_b = (const float*)d_in[9];
    const float* bhh_b = (const float*)d_in[10];
    const float* W_out = (const float*)d_in[11];
    const float* b_out = (const float*)d_in[12];
    const float* h0 = (const float*)d_in[13];
    const float* c0 = (const float*)d_in[14];
    const float* trans = (const float*)d_in[15];
    float* out = (float*)d_out;

    proj_kernel<<<512, 256>>>(sent, embed, Wih_f, bih_f, bhh_f, Wih_b, bih_b, bhh_b);
    lstm_kernel<<<16, 256>>>(Whh_f, Whh_b, h0, c0);
    feats_kernel<<<SEQT, 128>>>(W_out, b_out);
    crf_chunk_kernel<<<SEQT / 32, 144>>>(trans);
    crf_final_kernel<<<1, 256>>>(tags, trans, out);
}